// round 8
// baseline (speedup 1.0000x reference)
#include <cuda_runtime.h>
#include <cuda_fp16.h>
#include <cstdint>

#define N_NODES  50000
#define N_GRAPHS 128
#define HID      512
#define QELEMS   (N_GRAPHS * HID)
#define NWALK    12
#define NENT     (N_NODES * NWALK)
#define NSLICE   4

// ---------------- device scratch ----------------
__device__ int   g_pb[N_NODES];
__device__ int   g_base[N_NODES];
__device__ int   g_counts[N_GRAPHS];
__device__ int   g_cursors[N_GRAPHS];
__device__ int   g_off12[N_GRAPHS];
__device__ int   g_ent[NENT];
__device__ int   g_ctr[4];
__device__ uint4 g_xh4[N_NODES * 64];     // x in fp16: 64 uint4 (512 halves) per row
__device__ float g_Q[QELEMS];
__device__ float g_R0[QELEMS];
__device__ float g_R1[QELEMS];
__device__ float g_R2[QELEMS];
__device__ float g_P0[QELEMS];
__device__ float g_P1[QELEMS];

// ---------------- zero scratch ----------------
__global__ void k_zero() {
    int i = blockIdx.x * blockDim.x + threadIdx.x;
    uint4 z = make_uint4(0, 0, 0, 0);
    if (i < 16384) {
        ((uint4*)g_Q)[i]  = z;
        ((uint4*)g_R0)[i] = z;
        ((uint4*)g_R1)[i] = z;
        ((uint4*)g_R2)[i] = z;
    }
    if (i < N_GRAPHS) { g_counts[i] = 0; g_cursors[i] = 0; }
    if (i < 4) g_ctr[i] = 0;
}

// ---------------- fused: x->fp16 convert + path_batch/histogram ----------------
__global__ void k_cvt_pb(const float* __restrict__ x,
                         const int* __restrict__ walk2,
                         const int* __restrict__ batch) {
    int i = blockIdx.x * blockDim.x + threadIdx.x;
    if (i < N_NODES) {
        int g = batch[walk2[i]];          // walk2 row 0
        g_pb[i] = g;
        atomicAdd(&g_counts[g], 1);
    }
    if (i < N_NODES * 64) {
        const float4* x4 = (const float4*)x;
        float4 a = x4[2 * i];
        float4 b = x4[2 * i + 1];
        __half2 h0 = __floats2half2_rn(a.x, a.y);
        __half2 h1 = __floats2half2_rn(a.z, a.w);
        __half2 h2 = __floats2half2_rn(b.x, b.y);
        __half2 h3 = __floats2half2_rn(b.z, b.w);
        uint4 o;
        o.x = *(unsigned*)&h0; o.y = *(unsigned*)&h1;
        o.z = *(unsigned*)&h2; o.w = *(unsigned*)&h3;
        g_xh4[i] = o;
    }
}

// ---------------- parallel exclusive scan over 128 counts ----------------
__global__ void k_scan() {
    __shared__ int s[N_GRAPHS];
    int t = threadIdx.x;
    int v = g_counts[t];
    s[t] = v;
    __syncthreads();
    #pragma unroll
    for (int d = 1; d < N_GRAPHS; d <<= 1) {
        int u = (t >= d) ? s[t - d] : 0;
        __syncthreads();
        s[t] += u;
        __syncthreads();
    }
    g_off12[t] = (s[t] - v) * NWALK;
}

// ---------------- per-node entry base ----------------
__global__ void k_base() {
    int n = blockIdx.x * blockDim.x + threadIdx.x;
    if (n < N_NODES)
        g_base[n] = g_off12[g_pb[n]] + atomicAdd(&g_cursors[g_pb[n]], NWALK);
}

// ---------------- build entry list: one thread per entry ----------------
__global__ void k_build(const int* __restrict__ w2, const int* __restrict__ w3,
                        const int* __restrict__ w4) {
    int e = blockIdx.x * blockDim.x + threadIdx.x;
    if (e >= NENT) return;
    int n = e / NWALK;
    int r = e - n * NWALK;
    int j;
    if (r < 3)      j = w2[r * N_NODES + n];
    else if (r < 7) j = w3[(r - 3) * N_NODES + n];
    else            j = w4[(r - 7) * N_NODES + n];
    g_ent[g_base[n] + r] = j;
}

// ---------------- Q = A @ x : fp16 gather, tree-accumulate ----------------
// grid (N_GRAPHS, NSLICE), 256 threads = 4 row-groups of 64 lanes.
// Lane c owns 8 cols (one uint4 = 8 halves). 8-entry unroll, fp16 hadd2 tree,
// fp32 accumulation, smem cross-group reduce, then 512 atomics/CTA.
__global__ __launch_bounds__(256)
void k_gather() {
    __shared__ float s_red[4][512];

    const int g   = blockIdx.x;
    const int sl  = blockIdx.y;
    const int grp = threadIdx.x >> 6;
    const int c   = threadIdx.x & 63;

    const int start = g_off12[g];
    const int len   = g_counts[g] * NWALK;
    const int s0 = start + (len * sl) / NSLICE;
    const int s1 = start + (len * (sl + 1)) / NSLICE;

    float2 a0 = make_float2(0.f, 0.f), a1 = a0, a2 = a0, a3 = a0;

    int e = s0 + grp;
    // main loop: 8 entries per group per iteration (stride-4 interleave)
    for (; e + 28 < s1; e += 32) {
        int j0 = __ldg(&g_ent[e]);
        int j1 = __ldg(&g_ent[e + 4]);
        int j2 = __ldg(&g_ent[e + 8]);
        int j3 = __ldg(&g_ent[e + 12]);
        int j4 = __ldg(&g_ent[e + 16]);
        int j5 = __ldg(&g_ent[e + 20]);
        int j6 = __ldg(&g_ent[e + 24]);
        int j7 = __ldg(&g_ent[e + 28]);
        uint4 v0 = g_xh4[j0 * 64 + c];
        uint4 v1 = g_xh4[j1 * 64 + c];
        uint4 v2 = g_xh4[j2 * 64 + c];
        uint4 v3 = g_xh4[j3 * 64 + c];
        uint4 v4 = g_xh4[j4 * 64 + c];
        uint4 v5 = g_xh4[j5 * 64 + c];
        uint4 v6 = g_xh4[j6 * 64 + c];
        uint4 v7 = g_xh4[j7 * 64 + c];

        // fp16 tree sum of 8, per half2 component, then fp32 accumulate
        {
            __half2 t0 = __hadd2(__hadd2(*(__half2*)&v0.x, *(__half2*)&v1.x),
                                 __hadd2(*(__half2*)&v2.x, *(__half2*)&v3.x));
            __half2 t1 = __hadd2(__hadd2(*(__half2*)&v4.x, *(__half2*)&v5.x),
                                 __hadd2(*(__half2*)&v6.x, *(__half2*)&v7.x));
            float2 f = __half22float2(__hadd2(t0, t1));
            a0.x += f.x; a0.y += f.y;
        }
        {
            __half2 t0 = __hadd2(__hadd2(*(__half2*)&v0.y, *(__half2*)&v1.y),
                                 __hadd2(*(__half2*)&v2.y, *(__half2*)&v3.y));
            __half2 t1 = __hadd2(__hadd2(*(__half2*)&v4.y, *(__half2*)&v5.y),
                                 __hadd2(*(__half2*)&v6.y, *(__half2*)&v7.y));
            float2 f = __half22float2(__hadd2(t0, t1));
            a1.x += f.x; a1.y += f.y;
        }
        {
            __half2 t0 = __hadd2(__hadd2(*(__half2*)&v0.z, *(__half2*)&v1.z),
                                 __hadd2(*(__half2*)&v2.z, *(__half2*)&v3.z));
            __half2 t1 = __hadd2(__hadd2(*(__half2*)&v4.z, *(__half2*)&v5.z),
                                 __hadd2(*(__half2*)&v6.z, *(__half2*)&v7.z));
            float2 f = __half22float2(__hadd2(t0, t1));
            a2.x += f.x; a2.y += f.y;
        }
        {
            __half2 t0 = __hadd2(__hadd2(*(__half2*)&v0.w, *(__half2*)&v1.w),
                                 __hadd2(*(__half2*)&v2.w, *(__half2*)&v3.w));
            __half2 t1 = __hadd2(__hadd2(*(__half2*)&v4.w, *(__half2*)&v5.w),
                                 __hadd2(*(__half2*)&v6.w, *(__half2*)&v7.w));
            float2 f = __half22float2(__hadd2(t0, t1));
            a3.x += f.x; a3.y += f.y;
        }
    }
    // tail
    for (; e < s1; e += 4) {
        int j = __ldg(&g_ent[e]);
        uint4 v = g_xh4[j * 64 + c];
        float2 f0 = __half22float2(*(__half2*)&v.x);
        float2 f1 = __half22float2(*(__half2*)&v.y);
        float2 f2 = __half22float2(*(__half2*)&v.z);
        float2 f3 = __half22float2(*(__half2*)&v.w);
        a0.x += f0.x; a0.y += f0.y;
        a1.x += f1.x; a1.y += f1.y;
        a2.x += f2.x; a2.y += f2.y;
        a3.x += f3.x; a3.y += f3.y;
    }

    // cross-group smem reduce: 4 groups -> 1, then 512 atomics per CTA
    float* row = s_red[grp];
    row[c * 8 + 0] = a0.x; row[c * 8 + 1] = a0.y;
    row[c * 8 + 2] = a1.x; row[c * 8 + 3] = a1.y;
    row[c * 8 + 4] = a2.x; row[c * 8 + 5] = a2.y;
    row[c * 8 + 6] = a3.x; row[c * 8 + 7] = a3.y;
    __syncthreads();

    int t = threadIdx.x;
    #pragma unroll
    for (int q = 0; q < 2; q++) {
        int col = t + q * 256;
        float s = s_red[0][col] + s_red[1][col] + s_red[2][col] + s_red[3][col];
        atomicAdd(&g_Q[g * HID + col], s);
    }
}

// ---------------- fused layer: R = A@W (split-K) ; grid-sync ; epilogue ----------------
#define GK 32
#define GN 64
__global__ __launch_bounds__(256)
void k_layer(const float* __restrict__ A, const float* __restrict__ W,
             const float* __restrict__ bias, float* __restrict__ R,
             float* __restrict__ Pout, float* __restrict__ out, int layer) {
    __shared__ float sA[GK][129];
    __shared__ float sB[GK][GN];
    int nb = blockIdx.x;
    int kb = blockIdx.y;
    int tid = threadIdx.x;

    for (int i = tid; i < 128 * GK; i += 256) {
        int m = i >> 5;
        int k = i & 31;
        sA[k][m] = A[m * HID + kb * GK + k];
    }
    for (int i = tid; i < GK * GN; i += 256) {
        int k = i >> 6;
        int cc = i & 63;
        sB[k][cc] = W[(kb * GK + k) * HID + nb * GN + cc];
    }
    __syncthreads();

    int trow = tid >> 4;
    int tcol = tid & 15;
    float acc[8][4];
    #pragma unroll
    for (int i = 0; i < 8; i++)
        #pragma unroll
        for (int jj = 0; jj < 4; jj++) acc[i][jj] = 0.f;

    #pragma unroll
    for (int k = 0; k < GK; k++) {
        float a[8], b[4];
        #pragma unroll
        for (int i = 0; i < 8; i++) a[i] = sA[k][trow * 8 + i];
        #pragma unroll
        for (int jj = 0; jj < 4; jj++) b[jj] = sB[k][tcol * 4 + jj];
        #pragma unroll
        for (int i = 0; i < 8; i++)
            #pragma unroll
            for (int jj = 0; jj < 4; jj++) acc[i][jj] += a[i] * b[jj];
    }

    #pragma unroll
    for (int i = 0; i < 8; i++)
        #pragma unroll
        for (int jj = 0; jj < 4; jj++)
            atomicAdd(&R[(trow * 8 + i) * HID + nb * GN + tcol * 4 + jj], acc[i][jj]);

    // grid-wide arrival (128 CTAs, all resident)
    __threadfence();
    __syncthreads();
    if (tid == 0) {
        atomicAdd(&g_ctr[layer], 1);
        while (atomicAdd(&g_ctr[layer], 0) < 128) __nanosleep(64);
    }
    __syncthreads();
    __threadfence();

    // epilogue: each CTA owns 512 contiguous elements
    int bid = blockIdx.y * 8 + blockIdx.x;
    #pragma unroll
    for (int t = tid; t < 512; t += 256) {
        int i = bid * 512 + t;
        int m = i >> 9;
        int c = i & 511;
        float cnt = (float)g_counts[m];
        float v = R[i] + 12.0f * cnt * bias[c];
        if (Pout) Pout[i] = v;
        out[m * (3 * HID) + layer * HID + c] = v / fmaxf(cnt, 1.0f);
    }
}

// ---------------- launch ----------------
extern "C" void kernel_launch(void* const* d_in, const int* in_sizes, int n_in,
                              void* d_out, int out_size) {
    const float* x     = (const float*)d_in[0];
    const int*   walk2 = (const int*)  d_in[1];
    const int*   walk3 = (const int*)  d_in[2];
    const int*   walk4 = (const int*)  d_in[3];
    const int*   batch = (const int*)  d_in[4];
    const float* W0 = (const float*)d_in[5];
    const float* b0 = (const float*)d_in[6];
    const float* W1 = (const float*)d_in[7];
    const float* b1 = (const float*)d_in[8];
    const float* W2 = (const float*)d_in[9];
    const float* b2 = (const float*)d_in[10];
    float* out = (float*)d_out;

    float *pQ, *pR0, *pR1, *pR2, *pP0, *pP1;
    cudaGetSymbolAddress((void**)&pQ,  g_Q);
    cudaGetSymbolAddress((void**)&pR0, g_R0);
    cudaGetSymbolAddress((void**)&pR1, g_R1);
    cudaGetSymbolAddress((void**)&pR2, g_R2);
    cudaGetSymbolAddress((void**)&pP0, g_P0);
    cudaGetSymbolAddress((void**)&pP1, g_P1);

    k_zero<<<64, 256>>>();
    k_cvt_pb<<<(N_NODES * 64 + 255) / 256, 256>>>(x, walk2, batch);
    k_scan<<<1, N_GRAPHS>>>();
    k_base<<<(N_NODES + 255) / 256, 256>>>();
    k_build<<<(NENT + 255) / 256, 256>>>(walk2, walk3, walk4);
    k_gather<<<dim3(N_GRAPHS, NSLICE), 256>>>();

    k_layer<<<dim3(8, 16), 256>>>(pQ,  W0, b0, pR0, pP0, out, 0);
    k_layer<<<dim3(8, 16), 256>>>(pP0, W1, b1, pR1, pP1, out, 1);
    k_layer<<<dim3(8, 16), 256>>>(pP1, W2, b2, pR2, nullptr, out, 2);
}

// round 9
// speedup vs baseline: 1.1813x; 1.1813x over previous
#include <cuda_runtime.h>
#include <cuda_fp16.h>
#include <cstdint>

#define N_NODES  50000
#define N_GRAPHS 128
#define HID      512
#define QELEMS   (N_GRAPHS * HID)
#define NWALK    12
#define NODECAP  512                       // max nodes per graph (mean 391, 6-sigma safe)
#define ENTCAP   (NODECAP * NWALK)         // 6144 entries per graph slot
#define NSLICE   4

// ---------------- device scratch ----------------
__device__ int   g_pb[N_NODES];
__device__ int   g_pos[N_NODES];
__device__ int   g_counts[N_GRAPHS];
__device__ int   g_ent[N_GRAPHS * ENTCAP];
__device__ int   g_ctr[4];
__device__ uint4 g_xh4[N_NODES * 64];      // x in fp16: 64 uint4 (512 halves) per row
__device__ float g_Q[QELEMS];
__device__ float g_R0[QELEMS];
__device__ float g_R1[QELEMS];
__device__ float g_R2[QELEMS];
__device__ float g_P0[QELEMS];
__device__ float g_P1[QELEMS];

// ---------------- zero scratch ----------------
__global__ void k_zero() {
    int i = blockIdx.x * blockDim.x + threadIdx.x;
    uint4 z = make_uint4(0, 0, 0, 0);
    if (i < 16384) {
        ((uint4*)g_Q)[i]  = z;
        ((uint4*)g_R0)[i] = z;
        ((uint4*)g_R1)[i] = z;
        ((uint4*)g_R2)[i] = z;
    }
    if (i < N_GRAPHS) g_counts[i] = 0;
    if (i < 4) g_ctr[i] = 0;
}

// ---------------- path_batch + histogram + position ----------------
__global__ void k_pb(const int* __restrict__ walk2, const int* __restrict__ batch) {
    int n = blockIdx.x * blockDim.x + threadIdx.x;
    if (n < N_NODES) {
        int g = batch[walk2[n]];           // walk2 row 0
        g_pb[n]  = g;
        g_pos[n] = atomicAdd(&g_counts[g], 1);
    }
}

// ---------------- build entry list: one thread per entry, fixed slots ----------------
__global__ void k_build(const int* __restrict__ w2, const int* __restrict__ w3,
                        const int* __restrict__ w4) {
    int e = blockIdx.x * blockDim.x + threadIdx.x;
    if (e >= N_NODES * NWALK) return;
    int n = e / NWALK;
    int r = e - n * NWALK;
    int j;
    if (r < 3)      j = w2[r * N_NODES + n];
    else if (r < 7) j = w3[(r - 3) * N_NODES + n];
    else            j = w4[(r - 7) * N_NODES + n];
    g_ent[g_pb[n] * ENTCAP + g_pos[n] * NWALK + r] = j;
}

// ---------------- convert x to fp16 (runs on forked stream) ----------------
__global__ void k_cvt(const float* __restrict__ x) {
    int i = blockIdx.x * blockDim.x + threadIdx.x;
    if (i >= N_NODES * 64) return;
    const float4* x4 = (const float4*)x;
    float4 a = x4[2 * i];
    float4 b = x4[2 * i + 1];
    __half2 h0 = __floats2half2_rn(a.x, a.y);
    __half2 h1 = __floats2half2_rn(a.z, a.w);
    __half2 h2 = __floats2half2_rn(b.x, b.y);
    __half2 h3 = __floats2half2_rn(b.z, b.w);
    uint4 o;
    o.x = *(unsigned*)&h0; o.y = *(unsigned*)&h1;
    o.z = *(unsigned*)&h2; o.w = *(unsigned*)&h3;
    g_xh4[i] = o;
}

// ---------------- Q = A @ x : fp16 gather, fp32 accumulate, MLP=8 ----------------
// grid (N_GRAPHS, NSLICE), 256 threads = 4 row-groups of 64 lanes.
__global__ __launch_bounds__(256)
void k_gather() {
    __shared__ float s_red[4][512];

    const int g   = blockIdx.x;
    const int sl  = blockIdx.y;
    const int grp = threadIdx.x >> 6;
    const int c   = threadIdx.x & 63;

    const int start = g * ENTCAP;
    const int len   = g_counts[g] * NWALK;
    const int s0 = start + (len * sl) / NSLICE;
    const int s1 = start + (len * (sl + 1)) / NSLICE;

    float2 a0 = make_float2(0.f, 0.f), a1 = a0, a2 = a0, a3 = a0;

    int e = s0 + grp;
    for (; e + 28 < s1; e += 32) {
        int j0 = __ldg(&g_ent[e]);
        int j1 = __ldg(&g_ent[e + 4]);
        int j2 = __ldg(&g_ent[e + 8]);
        int j3 = __ldg(&g_ent[e + 12]);
        int j4 = __ldg(&g_ent[e + 16]);
        int j5 = __ldg(&g_ent[e + 20]);
        int j6 = __ldg(&g_ent[e + 24]);
        int j7 = __ldg(&g_ent[e + 28]);
        uint4 v0 = g_xh4[j0 * 64 + c];
        uint4 v1 = g_xh4[j1 * 64 + c];
        uint4 v2 = g_xh4[j2 * 64 + c];
        uint4 v3 = g_xh4[j3 * 64 + c];
        uint4 v4 = g_xh4[j4 * 64 + c];
        uint4 v5 = g_xh4[j5 * 64 + c];
        uint4 v6 = g_xh4[j6 * 64 + c];
        uint4 v7 = g_xh4[j7 * 64 + c];
        #pragma unroll
        for (int q = 0; q < 8; q++) {
            uint4 v = (q == 0) ? v0 : (q == 1) ? v1 : (q == 2) ? v2 : (q == 3) ? v3
                    : (q == 4) ? v4 : (q == 5) ? v5 : (q == 6) ? v6 : v7;
            float2 f0 = __half22float2(*(__half2*)&v.x);
            float2 f1 = __half22float2(*(__half2*)&v.y);
            float2 f2 = __half22float2(*(__half2*)&v.z);
            float2 f3 = __half22float2(*(__half2*)&v.w);
            a0.x += f0.x; a0.y += f0.y;
            a1.x += f1.x; a1.y += f1.y;
            a2.x += f2.x; a2.y += f2.y;
            a3.x += f3.x; a3.y += f3.y;
        }
    }
    for (; e < s1; e += 4) {
        int j = __ldg(&g_ent[e]);
        uint4 v = g_xh4[j * 64 + c];
        float2 f0 = __half22float2(*(__half2*)&v.x);
        float2 f1 = __half22float2(*(__half2*)&v.y);
        float2 f2 = __half22float2(*(__half2*)&v.z);
        float2 f3 = __half22float2(*(__half2*)&v.w);
        a0.x += f0.x; a0.y += f0.y;
        a1.x += f1.x; a1.y += f1.y;
        a2.x += f2.x; a2.y += f2.y;
        a3.x += f3.x; a3.y += f3.y;
    }

    // cross-group smem reduce, then 512 atomics per CTA
    float* row = s_red[grp];
    row[c * 8 + 0] = a0.x; row[c * 8 + 1] = a0.y;
    row[c * 8 + 2] = a1.x; row[c * 8 + 3] = a1.y;
    row[c * 8 + 4] = a2.x; row[c * 8 + 5] = a2.y;
    row[c * 8 + 6] = a3.x; row[c * 8 + 7] = a3.y;
    __syncthreads();

    int t = threadIdx.x;
    #pragma unroll
    for (int q = 0; q < 2; q++) {
        int col = t + q * 256;
        float s = s_red[0][col] + s_red[1][col] + s_red[2][col] + s_red[3][col];
        atomicAdd(&g_Q[g * HID + col], s);
    }
}

// ---------------- fused layer: R = A@W (split-K) ; grid-sync ; epilogue ----------------
#define GK 32
#define GN 64
__global__ __launch_bounds__(256)
void k_layer(const float* __restrict__ A, const float* __restrict__ W,
             const float* __restrict__ bias, float* __restrict__ R,
             float* __restrict__ Pout, float* __restrict__ out, int layer) {
    __shared__ float sA[GK][129];
    __shared__ float sB[GK][GN];
    int nb = blockIdx.x;
    int kb = blockIdx.y;
    int tid = threadIdx.x;

    for (int i = tid; i < 128 * GK; i += 256) {
        int m = i >> 5;
        int k = i & 31;
        sA[k][m] = A[m * HID + kb * GK + k];
    }
    for (int i = tid; i < GK * GN; i += 256) {
        int k = i >> 6;
        int cc = i & 63;
        sB[k][cc] = W[(kb * GK + k) * HID + nb * GN + cc];
    }
    __syncthreads();

    int trow = tid >> 4;
    int tcol = tid & 15;
    float acc[8][4];
    #pragma unroll
    for (int i = 0; i < 8; i++)
        #pragma unroll
        for (int jj = 0; jj < 4; jj++) acc[i][jj] = 0.f;

    #pragma unroll
    for (int k = 0; k < GK; k++) {
        float a[8], b[4];
        #pragma unroll
        for (int i = 0; i < 8; i++) a[i] = sA[k][trow * 8 + i];
        #pragma unroll
        for (int jj = 0; jj < 4; jj++) b[jj] = sB[k][tcol * 4 + jj];
        #pragma unroll
        for (int i = 0; i < 8; i++)
            #pragma unroll
            for (int jj = 0; jj < 4; jj++) acc[i][jj] += a[i] * b[jj];
    }

    #pragma unroll
    for (int i = 0; i < 8; i++)
        #pragma unroll
        for (int jj = 0; jj < 4; jj++)
            atomicAdd(&R[(trow * 8 + i) * HID + nb * GN + tcol * 4 + jj], acc[i][jj]);

    // grid-wide arrival (128 CTAs, all resident)
    __threadfence();
    __syncthreads();
    if (tid == 0) {
        atomicAdd(&g_ctr[layer], 1);
        while (atomicAdd(&g_ctr[layer], 0) < 128) __nanosleep(64);
    }
    __syncthreads();
    __threadfence();

    // epilogue: each CTA owns 512 contiguous elements
    int bid = blockIdx.y * 8 + blockIdx.x;
    #pragma unroll
    for (int t = tid; t < 512; t += 256) {
        int i = bid * 512 + t;
        int m = i >> 9;
        int c = i & 511;
        float cnt = (float)g_counts[m];
        float v = R[i] + 12.0f * cnt * bias[c];
        if (Pout) Pout[i] = v;
        out[m * (3 * HID) + layer * HID + c] = v / fmaxf(cnt, 1.0f);
    }
}

// ---------------- launch ----------------
extern "C" void kernel_launch(void* const* d_in, const int* in_sizes, int n_in,
                              void* d_out, int out_size) {
    const float* x     = (const float*)d_in[0];
    const int*   walk2 = (const int*)  d_in[1];
    const int*   walk3 = (const int*)  d_in[2];
    const int*   walk4 = (const int*)  d_in[3];
    const int*   batch = (const int*)  d_in[4];
    const float* W0 = (const float*)d_in[5];
    const float* b0 = (const float*)d_in[6];
    const float* W1 = (const float*)d_in[7];
    const float* b1 = (const float*)d_in[8];
    const float* W2 = (const float*)d_in[9];
    const float* b2 = (const float*)d_in[10];
    float* out = (float*)d_out;

    float *pQ, *pR0, *pR1, *pR2, *pP0, *pP1;
    cudaGetSymbolAddress((void**)&pQ,  g_Q);
    cudaGetSymbolAddress((void**)&pR0, g_R0);
    cudaGetSymbolAddress((void**)&pR1, g_R1);
    cudaGetSymbolAddress((void**)&pR2, g_R2);
    cudaGetSymbolAddress((void**)&pP0, g_P0);
    cudaGetSymbolAddress((void**)&pP1, g_P1);

    // fork: x->fp16 convert runs concurrently with zero/pb/build (disjoint data)
    cudaStream_t s2;
    cudaEvent_t eFork, eJoin;
    cudaStreamCreateWithFlags(&s2, cudaStreamNonBlocking);
    cudaEventCreateWithFlags(&eFork, cudaEventDisableTiming);
    cudaEventCreateWithFlags(&eJoin, cudaEventDisableTiming);

    cudaEventRecord(eFork, 0);
    cudaStreamWaitEvent(s2, eFork, 0);
    k_cvt<<<(N_NODES * 64 + 255) / 256, 256, 0, s2>>>(x);
    cudaEventRecord(eJoin, s2);

    k_zero<<<64, 256>>>();
    k_pb<<<(N_NODES + 255) / 256, 256>>>(walk2, batch);
    k_build<<<(N_NODES * NWALK + 255) / 256, 256>>>(walk2, walk3, walk4);

    cudaStreamWaitEvent(0, eJoin, 0);
    k_gather<<<dim3(N_GRAPHS, NSLICE), 256>>>();

    k_layer<<<dim3(8, 16), 256>>>(pQ,  W0, b0, pR0, pP0, out, 0);
    k_layer<<<dim3(8, 16), 256>>>(pP0, W1, b1, pR1, pP1, out, 1);
    k_layer<<<dim3(8, 16), 256>>>(pP1, W2, b2, pR2, nullptr, out, 2);

    cudaEventDestroy(eFork);
    cudaEventDestroy(eJoin);
    cudaStreamDestroy(s2);
}